// round 15
// baseline (speedup 1.0000x reference)
#include <cuda_runtime.h>
#include <math.h>

#define SBK   2048
#define PASTK 64
#define FUTK  16
#define N1K   (SBK*PASTK)
#define N2K   (SBK*FUTK)
#define E1K   (N1K*8)
#define E2K   (N2K*8)

// ---------------- device scratch (stride-36 padded feature buffers) ----------------
__device__ __align__(16) float g_x[N1K*36];      // pre out x1 (stride 36, ch35 = 0)
__device__ __align__(16) float g_x2p[N2K*36];    // pre out x2 (stride 36, ch35 = 0)
__device__ __align__(16) float g_bufA[N1K*64];   // hw2 (stride 36) / scalar scratch
__device__ __align__(16) float g_bufC[N1K*64];   // x1g (stride 36)
__device__ float g_dinv1[N1K];
__device__ float g_dinv2[N2K];
__device__ float g_theta[34*34];
__device__ __align__(16) float g_x2n[N2K*36];    // x2 updated (stride 36, ch35 = 0)
__device__ int g_counts1[N1K];
__device__ int g_rowptr1[N1K];
__device__ int g_cursor1[N1K];
__device__ int g_eidx1[E1K];
__device__ int g_counts2[N2K];
__device__ int g_rowptr2[N2K];
__device__ int g_cursor2[N2K];
__device__ int g_eidx2[E2K];
__device__ int g_partials[128];

// ---------------- misc: A + theta ---------------------------------------------------
__global__ void misc_kernel(const float* __restrict__ M, float* __restrict__ A,
                            const float* __restrict__ kerW, float* __restrict__ th)
{
    __shared__ float sM[80*26];
    int tid = threadIdx.x;
    for (int i = tid; i < 80*26; i += blockDim.x) sM[i] = M[i];
    __syncthreads();
    for (int idx = tid; idx < 34*34; idx += blockDim.x) {
        int i = idx / 34, j = idx - i*34;
        float s = 0.f;
        #pragma unroll 8
        for (int k = 0; k < 128; k++) s = fmaf(kerW[i*128+k], kerW[j*128+k], s);
        th[idx] = s;
    }
    if (tid < 80) {
        int i = tid;
        float mx = -INFINITY;
        for (int j = 0; j <= i; j++) {
            float s = 0.f;
            #pragma unroll
            for (int k = 0; k < 26; k++) s = fmaf(sM[i*26+k], sM[j*26+k], s);
            s = fmaxf(s, 0.f);
            mx = fmaxf(mx, s);
        }
        float sum = 0.f;
        for (int j = 0; j <= i; j++) {
            float s = 0.f;
            #pragma unroll
            for (int k = 0; k < 26; k++) s = fmaf(sM[i*26+k], sM[j*26+k], s);
            s = fmaxf(s, 0.f);
            float e = expf(s - mx);
            sum += e;
            A[i*80+j] = e;
        }
        float inv = 1.f / sum;
        for (int j = 0; j <= i; j++) A[i*80+j] *= inv;
        for (int j = i+1; j < 80; j++) A[i*80+j] = 0.f;
    }
}

// ---------------- pre MLP: 8 rows/warp, out stride 36 (ch35 = 0) -------------------
__global__ void __launch_bounds__(256, 2)
pre_kernel(const int* __restrict__ cat, const float* __restrict__ num, int nrows,
           const float* __restrict__ W1, const float* __restrict__ b1,
           const float* __restrict__ W2, const float* __restrict__ b2,
           const float* __restrict__ W3, const float* __restrict__ b3,
           const float* __restrict__ emb0, const float* __restrict__ emb1,
           const float* __restrict__ emb2, float* __restrict__ out)
{
    extern __shared__ float smem[];
    float* sW1 = smem;
    float* sW2 = sW1 + 35*128;
    float* sW3 = sW2 + 128*128;
    float* sb1 = sW3 + 128*34;
    float* sb2 = sb1 + 128;
    float* sb3 = sb2 + 128;
    int tid = threadIdx.x;
    for (int i = tid; i < 35*128;  i += blockDim.x) sW1[i] = W1[i];
    for (int i = tid; i < 128*128; i += blockDim.x) sW2[i] = W2[i];
    for (int i = tid; i < 128*34;  i += blockDim.x) sW3[i] = W3[i];
    if (tid < 128) { sb1[tid] = b1[tid]; sb2[tid] = b2[tid]; }
    if (tid < 34) sb3[tid] = b3[tid];
    __syncthreads();
    const int lane = tid & 31, warp = tid >> 5, nw = blockDim.x >> 5;
    const unsigned FULL = 0xffffffffu;
    const int R = 8;
    const int rstep = gridDim.x*nw*R;
    for (int r0 = (blockIdx.x*nw + warp)*R; r0 < nrows; r0 += rstep) {
        float oa[R], ob[R];
        #pragma unroll
        for (int j = 0; j < R; j++) {
            int r = min(r0 + j, nrows - 1);
            int c0 = cat[3*r], c1 = cat[3*r+1], c2 = cat[3*r+2];
            float v;
            if (lane < 16)      v = emb0[c0*16 + lane];
            else if (lane < 24) v = emb1[c1*8 + lane - 16];
            else                v = emb2[c2*8 + lane - 24];
            oa[j] = v;
            ob[j] = (lane < 3) ? num[3*r + lane] : 0.f;
        }
        float4 a[R];
        {
            float4 bias = ((const float4*)sb1)[lane];
            #pragma unroll
            for (int j = 0; j < R; j++) a[j] = bias;
            #pragma unroll
            for (int k = 0; k < 35; k++) {
                float4 w = ((const float4*)(sW1 + k*128))[lane];
                #pragma unroll
                for (int j = 0; j < R; j++) {
                    float xv = (k < 32) ? __shfl_sync(FULL, oa[j], k)
                                        : __shfl_sync(FULL, ob[j], k - 32);
                    a[j].x = fmaf(xv, w.x, a[j].x); a[j].y = fmaf(xv, w.y, a[j].y);
                    a[j].z = fmaf(xv, w.z, a[j].z); a[j].w = fmaf(xv, w.w, a[j].w);
                }
            }
            #pragma unroll
            for (int j = 0; j < R; j++) {
                a[j].x = fmaxf(a[j].x,0.f); a[j].y = fmaxf(a[j].y,0.f);
                a[j].z = fmaxf(a[j].z,0.f); a[j].w = fmaxf(a[j].w,0.f);
            }
        }
        float4 bb[R];
        {
            float4 bias = ((const float4*)sb2)[lane];
            #pragma unroll
            for (int j = 0; j < R; j++) bb[j] = bias;
            #pragma unroll 4
            for (int k = 0; k < 128; k++) {
                float4 w = ((const float4*)(sW2 + k*128))[lane];
                const int srcl = k >> 2;
                #pragma unroll
                for (int j = 0; j < R; j++) {
                    float comp = ((k & 3) == 0) ? a[j].x : ((k & 3) == 1) ? a[j].y
                               : ((k & 3) == 2) ? a[j].z : a[j].w;
                    float hv = __shfl_sync(FULL, comp, srcl);
                    bb[j].x = fmaf(hv, w.x, bb[j].x); bb[j].y = fmaf(hv, w.y, bb[j].y);
                    bb[j].z = fmaf(hv, w.z, bb[j].z); bb[j].w = fmaf(hv, w.w, bb[j].w);
                }
            }
            #pragma unroll
            for (int j = 0; j < R; j++) {
                bb[j].x = fmaxf(bb[j].x,0.f); bb[j].y = fmaxf(bb[j].y,0.f);
                bb[j].z = fmaxf(bb[j].z,0.f); bb[j].w = fmaxf(bb[j].w,0.f);
            }
        }
        {
            const int j0 = lane, j1 = lane + 32;
            const bool has1 = (j1 < 34);
            float acc0[R], acc1[R];
            #pragma unroll
            for (int j = 0; j < R; j++) { acc0[j] = 0.f; acc1[j] = 0.f; }
            #pragma unroll 4
            for (int k = 0; k < 128; k++) {
                float w0 = sW3[k*34 + j0];
                float w1 = has1 ? sW3[k*34 + j1] : 0.f;
                const int srcl = k >> 2;
                #pragma unroll
                for (int j = 0; j < R; j++) {
                    float comp = ((k & 3) == 0) ? bb[j].x : ((k & 3) == 1) ? bb[j].y
                               : ((k & 3) == 2) ? bb[j].z : bb[j].w;
                    float hv = __shfl_sync(FULL, comp, srcl);
                    acc0[j] = fmaf(hv, w0, acc0[j]);
                    acc1[j] = fmaf(hv, w1, acc1[j]);
                }
            }
            #pragma unroll
            for (int j = 0; j < R; j++) {
                int r = min(r0 + j, nrows - 1);
                float n2v = __shfl_sync(FULL, ob[j], 2);
                float* orow = out + (size_t)r*36;
                orow[j0] = acc0[j] + sb3[j0];
                if (has1) orow[j1] = acc1[j] + sb3[j1];
                if (lane == 0) { orow[34] = n2v; orow[35] = 0.f; }
            }
        }
    }
}

// ---------------- merged CSR build ---------------------------------------------------
__global__ void zero_both_kernel(int* __restrict__ c1, int n1, int* __restrict__ c2, int n2)
{
    for (int i = blockIdx.x*blockDim.x + threadIdx.x; i < n1 + n2; i += gridDim.x*blockDim.x) {
        if (i < n1) c1[i] = 0; else c2[i - n1] = 0;
    }
}
__global__ void count_both_kernel(const int* __restrict__ d1, int E1,
                                  const int* __restrict__ d2, int E2,
                                  int* __restrict__ c1, int* __restrict__ c2)
{
    int e = blockIdx.x*blockDim.x + threadIdx.x;
    if (e < E1) atomicAdd(&c1[d1[e]], 1);
    else if (e - E1 < E2) atomicAdd(&c2[d2[e - E1]], 1);
}
__global__ void scan1_both_kernel(const int* __restrict__ in1, int* __restrict__ out1, int n1, int B1,
                                  const int* __restrict__ in2, int* __restrict__ out2, int n2,
                                  int* __restrict__ partials)
{
    __shared__ int sdata[1024];
    int tid = threadIdx.x;
    const int* in; int* outp; int n; int blk; int* part;
    if ((int)blockIdx.x < B1) { in = in1; outp = out1; n = n1; blk = blockIdx.x; part = partials; }
    else { in = in2; outp = out2; n = n2; blk = blockIdx.x - B1; part = partials + 64; }
    int base = blk*4096 + tid*4;
    int v[4];
    #pragma unroll
    for (int j = 0; j < 4; j++) v[j] = (base + j < n) ? in[base + j] : 0;
    int tsum = v[0] + v[1] + v[2] + v[3];
    sdata[tid] = tsum;
    __syncthreads();
    for (int off = 1; off < 1024; off <<= 1) {
        int add = (tid >= off) ? sdata[tid - off] : 0;
        __syncthreads();
        sdata[tid] += add;
        __syncthreads();
    }
    int run = sdata[tid] - tsum;
    #pragma unroll
    for (int j = 0; j < 4; j++) {
        if (base + j < n) outp[base + j] = run;
        run += v[j];
    }
    if (tid == 1023) part[blk] = sdata[1023];
}
__global__ void scan2_both_kernel(int* __restrict__ partials, int B1, int B2)
{
    int tid = threadIdx.x;
    int w = tid >> 5, lane = tid & 31;
    const unsigned FULL = 0xffffffffu;
    int* p = partials + (w ? 64 : 0);
    int B = w ? B2 : B1;
    if (w < 2) {
        int orig = (lane < B) ? p[lane] : 0;
        int v = orig;
        #pragma unroll
        for (int off = 1; off < 32; off <<= 1) {
            int t = __shfl_up_sync(FULL, v, off);
            if (lane >= off) v += t;
        }
        if (lane < B) p[lane] = v - orig;
    }
}
__global__ void scan3_both_kernel(int* __restrict__ rp1, const int* __restrict__ c1,
                                  int* __restrict__ cur1, float* __restrict__ dv1, int n1,
                                  int* __restrict__ rp2, const int* __restrict__ c2,
                                  int* __restrict__ cur2, float* __restrict__ dv2, int n2,
                                  const int* __restrict__ partials)
{
    int i = blockIdx.x*blockDim.x + threadIdx.x;
    if (i < n1) {
        int rp = rp1[i] + partials[i >> 12];
        rp1[i] = rp; cur1[i] = rp;
        dv1[i] = rsqrtf(1.0f + (float)c1[i]);
    } else if (i - n1 < n2) {
        int j = i - n1;
        int rp = rp2[j] + partials[64 + (j >> 12)];
        rp2[j] = rp; cur2[j] = rp;
        dv2[j] = rsqrtf(1.0f + (float)c2[j]);
    }
}
__global__ void scatter_both_kernel(const int* __restrict__ s1, const int* __restrict__ d1, int E1,
                                    int* __restrict__ cur1, int* __restrict__ ei1,
                                    const int* __restrict__ s2, const int* __restrict__ d2, int E2,
                                    int* __restrict__ cur2, int* __restrict__ ei2)
{
    int e = blockIdx.x*blockDim.x + threadIdx.x;
    if (e < E1) {
        int pos = atomicAdd(&cur1[d1[e]], 1);
        ei1[pos] = s1[e];
    } else if (e - E1 < E2) {
        int j = e - E1;
        int pos = atomicAdd(&cur2[d2[j]], 1);
        ei2[pos] = s2[j];
    }
}

// ---------------- fused GCN layer-1 + W2, float2 lanes (input stride 36) -----------
__global__ void __launch_bounds__(512)
gather_mm35_w2_kernel(const float* __restrict__ x /*stride 36, ch35=0*/,
                      const int* __restrict__ rowptr, const int* __restrict__ counts,
                      const int* __restrict__ eidx, const float* __restrict__ dinv,
                      const float* __restrict__ W1, const float* __restrict__ b1,
                      const float* __restrict__ W2, int dout2,
                      float* __restrict__ out, int n)
{
    __shared__ float sW1[35*64];
    __shared__ float sb1[64];
    __shared__ float sW2[64*34];
    int tid = threadIdx.x;
    for (int i = tid; i < 35*64; i += blockDim.x) sW1[i] = W1[i];
    if (tid < 64) sb1[tid] = b1[tid];
    for (int i = tid; i < 64*dout2; i += blockDim.x) sW2[i] = W2[i];
    __syncthreads();
    const unsigned FULL = 0xffffffffu;
    int gw = (blockIdx.x*blockDim.x + tid) >> 5;
    int lane = tid & 31;
    if (gw >= n) return;
    const int r = gw;
    const int cl = (lane < 18) ? lane : 0;   // lane owns channels {2cl, 2cl+1}
    float dr = dinv[r];
    float d2 = dr*dr;
    const float2* hr = (const float2*)(x + (size_t)r*36);
    float2 sv = __ldg(&hr[cl]);
    float aLo = sv.x*d2, aHi = sv.y*d2;
    float bLo = 0.f, bHi = 0.f, cLo = 0.f, cHi = 0.f, eLo = 0.f, eHi = 0.f;
    int start = rowptr[r], cnt = counts[r];
    int i = 0;
    for (; i + 4 <= cnt; i += 4) {
        int s0 = __ldg(&eidx[start+i]);
        int s1 = __ldg(&eidx[start+i+1]);
        int s2 = __ldg(&eidx[start+i+2]);
        int s3 = __ldg(&eidx[start+i+3]);
        float f0 = __ldg(&dinv[s0])*dr;
        float f1 = __ldg(&dinv[s1])*dr;
        float f2 = __ldg(&dinv[s2])*dr;
        float f3 = __ldg(&dinv[s3])*dr;
        float2 v0 = __ldg(&((const float2*)(x + (size_t)s0*36))[cl]);
        float2 v1 = __ldg(&((const float2*)(x + (size_t)s1*36))[cl]);
        float2 v2 = __ldg(&((const float2*)(x + (size_t)s2*36))[cl]);
        float2 v3 = __ldg(&((const float2*)(x + (size_t)s3*36))[cl]);
        aLo = fmaf(f0, v0.x, aLo); aHi = fmaf(f0, v0.y, aHi);
        bLo = fmaf(f1, v1.x, bLo); bHi = fmaf(f1, v1.y, bHi);
        cLo = fmaf(f2, v2.x, cLo); cHi = fmaf(f2, v2.y, cHi);
        eLo = fmaf(f3, v3.x, eLo); eHi = fmaf(f3, v3.y, eHi);
    }
    for (; i < cnt; i++) {
        int s = __ldg(&eidx[start+i]);
        float f = __ldg(&dinv[s])*dr;
        float2 v = __ldg(&((const float2*)(x + (size_t)s*36))[cl]);
        aLo = fmaf(f, v.x, aLo); aHi = fmaf(f, v.y, aHi);
    }
    aLo += bLo + cLo + eLo;
    aHi += bHi + cHi + eHi;
    // mm1: h[c] = relu(b1[c] + sum_k agg[k]*W1[k][c]); agg[k] at lane k/2, comp k%2
    float o0 = sb1[lane], o1 = sb1[lane + 32];
    #pragma unroll
    for (int k = 0; k < 35; k++) {
        float xv = __shfl_sync(FULL, (k & 1) ? aHi : aLo, k >> 1);
        o0 = fmaf(xv, sW1[k*64 + lane], o0);
        o1 = fmaf(xv, sW1[k*64 + 32 + lane], o1);
    }
    o0 = fmaxf(o0, 0.f); o1 = fmaxf(o1, 0.f);
    if (dout2 == 34) {
        const bool hasHi = (lane < 2);
        float z0 = 0.f, z1 = 0.f;
        #pragma unroll 8
        for (int k = 0; k < 64; k++) {
            float hv = (k < 32) ? __shfl_sync(FULL, o0, k)
                                : __shfl_sync(FULL, o1, k - 32);
            z0 = fmaf(hv, sW2[k*34 + lane], z0);
            if (hasHi) z1 = fmaf(hv, sW2[k*34 + 32 + lane], z1);
        }
        float* orow = out + (size_t)r*36;
        orow[lane] = z0;
        if (hasHi) orow[lane + 32] = z1;
    } else {
        float z = o0*sW2[lane] + o1*sW2[lane + 32];
        #pragma unroll
        for (int off = 16; off; off >>= 1) z += __shfl_xor_sync(FULL, z, off);
        if (lane == 0) out[r] = z;
    }
}

// ---------------- 34-dim gather + bias, float2 lanes (stride 36 in/out) -------------
__global__ void __launch_bounds__(512)
gather34_kernel(const float* __restrict__ h /*stride 36, ch34..35 unused*/,
                const int* __restrict__ rowptr, const int* __restrict__ counts,
                const int* __restrict__ eidx, const float* __restrict__ dinv,
                const float* __restrict__ bias, float* __restrict__ out /*stride 36*/,
                int n)
{
    int gw = (blockIdx.x*blockDim.x + threadIdx.x) >> 5;
    int lane = threadIdx.x & 31;
    if (gw >= n) return;
    const int r = gw;
    const int cl = (lane < 17) ? lane : 0;   // channels {2cl, 2cl+1}, 34 total
    float dr = dinv[r];
    float d2 = dr*dr;
    const float2* hr = (const float2*)(h + (size_t)r*36);
    float2 sv = __ldg(&hr[cl]);
    float aLo = sv.x*d2, aHi = sv.y*d2;
    float bLo = 0.f, bHi = 0.f, cLo = 0.f, cHi = 0.f, eLo = 0.f, eHi = 0.f;
    int start = rowptr[r], cnt = counts[r];
    int i = 0;
    for (; i + 4 <= cnt; i += 4) {
        int s0 = __ldg(&eidx[start+i]);
        int s1 = __ldg(&eidx[start+i+1]);
        int s2 = __ldg(&eidx[start+i+2]);
        int s3 = __ldg(&eidx[start+i+3]);
        float f0 = __ldg(&dinv[s0])*dr;
        float f1 = __ldg(&dinv[s1])*dr;
        float f2 = __ldg(&dinv[s2])*dr;
        float f3 = __ldg(&dinv[s3])*dr;
        float2 v0 = __ldg(&((const float2*)(h + (size_t)s0*36))[cl]);
        float2 v1 = __ldg(&((const float2*)(h + (size_t)s1*36))[cl]);
        float2 v2 = __ldg(&((const float2*)(h + (size_t)s2*36))[cl]);
        float2 v3 = __ldg(&((const float2*)(h + (size_t)s3*36))[cl]);
        aLo = fmaf(f0, v0.x, aLo); aHi = fmaf(f0, v0.y, aHi);
        bLo = fmaf(f1, v1.x, bLo); bHi = fmaf(f1, v1.y, bHi);
        cLo = fmaf(f2, v2.x, cLo); cHi = fmaf(f2, v2.y, cHi);
        eLo = fmaf(f3, v3.x, eLo); eHi = fmaf(f3, v3.y, eHi);
    }
    for (; i < cnt; i++) {
        int s = __ldg(&eidx[start+i]);
        float f = __ldg(&dinv[s])*dr;
        float2 v = __ldg(&((const float2*)(h + (size_t)s*36))[cl]);
        aLo = fmaf(f, v.x, aLo); aHi = fmaf(f, v.y, aHi);
    }
    if (lane < 17) {
        float2 o;
        o.x = aLo + bLo + cLo + eLo + __ldg(&bias[2*cl]);
        o.y = aHi + bHi + cHi + eHi + __ldg(&bias[2*cl + 1]);
        ((float2*)(out + (size_t)r*36))[cl] = o;
    }
}

__global__ void gather1_kernel(const float* __restrict__ h,
                               const int* __restrict__ rowptr, const int* __restrict__ counts,
                               const int* __restrict__ eidx, const float* __restrict__ dinv,
                               const float* __restrict__ bias, float* __restrict__ out, int n)
{
    int r = blockIdx.x*blockDim.x + threadIdx.x;
    if (r >= n) return;
    float dr = dinv[r];
    float a = h[r]*dr*dr, b = 0.f, c = 0.f, e = 0.f;
    int start = rowptr[r], cnt = counts[r];
    int i = 0;
    for (; i + 4 <= cnt; i += 4) {
        int s0 = __ldg(&eidx[start+i]);
        int s1 = __ldg(&eidx[start+i+1]);
        int s2 = __ldg(&eidx[start+i+2]);
        int s3 = __ldg(&eidx[start+i+3]);
        a = fmaf(__ldg(&dinv[s0])*dr, __ldg(&h[s0]), a);
        b = fmaf(__ldg(&dinv[s1])*dr, __ldg(&h[s1]), b);
        c = fmaf(__ldg(&dinv[s2])*dr, __ldg(&h[s2]), c);
        e = fmaf(__ldg(&dinv[s3])*dr, __ldg(&h[s3]), e);
    }
    for (; i < cnt; i++) {
        int s = __ldg(&eidx[start+i]);
        a = fmaf(__ldg(&dinv[s])*dr, __ldg(&h[s]), a);
    }
    out[r] = a + b + c + e + bias[0];
}

// ---------------- alpha (register-tiled; x2p/xfull stride 36; x2n stride 36) --------
__global__ void __launch_bounds__(256)
alpha_kernel(const float* __restrict__ x1g /*stride 36*/,
             const float* __restrict__ x2p /*stride 36*/,
             const float* __restrict__ xfull /*stride 36*/,
             const float* __restrict__ theta,
             const float* __restrict__ A,
             const float* __restrict__ smoothing,
             float* __restrict__ x2n /*stride 36*/)
{
    __shared__ float sxk[80*36];
    __shared__ float sth[34*34];
    __shared__ float sG[80*36];
    __shared__ float ss[80];
    __shared__ float syk[64];
    __shared__ float sal[16*64];
    __shared__ float syh[16];
    const int b = blockIdx.x, tid = threadIdx.x;
    const int NT = 256;
    for (int i = tid; i < 34*34; i += NT) sth[i] = theta[i];
    for (int i = tid; i < 80*34; i += NT) {
        int n = i / 34, o = i - n*34;
        float v = (n < 64) ? x1g[(size_t)(b*64 + n)*36 + o]
                           : x2p[(size_t)(b*16 + (n - 64))*36 + o];
        sxk[n*36 + o] = v;
    }
    if (tid < 64) syk[tid] = xfull[(size_t)(b*64 + tid)*36 + 34];
    __syncthreads();
    for (int t = tid; t < 180; t += NT) {
        int ng = t / 9, og = t - ng*9;
        int n0 = ng*4, o0 = og*4;
        float acc[4][4];
        #pragma unroll
        for (int ii = 0; ii < 4; ii++)
            #pragma unroll
            for (int jj = 0; jj < 4; jj++) acc[ii][jj] = 0.f;
        #pragma unroll 2
        for (int k = 0; k < 34; k++) {
            float wv[4], xv[4];
            #pragma unroll
            for (int ii = 0; ii < 4; ii++) wv[ii] = sth[min(o0+ii,33)*34 + k];
            #pragma unroll
            for (int jj = 0; jj < 4; jj++) xv[jj] = sxk[(n0+jj)*36 + k];
            #pragma unroll
            for (int ii = 0; ii < 4; ii++)
                #pragma unroll
                for (int jj = 0; jj < 4; jj++) acc[ii][jj] = fmaf(wv[ii], xv[jj], acc[ii][jj]);
        }
        #pragma unroll
        for (int ii = 0; ii < 4; ii++) {
            if (o0 + ii < 34)
                #pragma unroll
                for (int jj = 0; jj < 4; jj++) sG[(n0+jj)*36 + o0 + ii] = acc[ii][jj];
        }
    }
    __syncthreads();
    for (int nn = tid; nn < 80; nn += NT) {
        float s = 0.f;
        #pragma unroll 2
        for (int k = 0; k < 34; k++) s = fmaf(sG[nn*36+k], sxk[nn*36+k], s);
        ss[nn] = s;
    }
    __syncthreads();
    float sm0 = smoothing[0];
    float sig = 1.f / (1.f + expf(-sm0));
    float scale = -0.5f / (sig * 0.01f);
    if (tid < 128) {
        int qg = tid >> 4, pg = tid & 15;
        int q0 = qg*2, p0 = pg*4;
        float acc[2][4];
        #pragma unroll
        for (int qi = 0; qi < 2; qi++)
            #pragma unroll
            for (int jj = 0; jj < 4; jj++) acc[qi][jj] = 0.f;
        const float* gq0 = sG + (64+q0)*36;
        const float* gq1 = sG + (64+q0+1)*36;
        #pragma unroll 2
        for (int k = 0; k < 34; k++) {
            float g0 = gq0[k], g1 = gq1[k];
            float xv[4];
            #pragma unroll
            for (int jj = 0; jj < 4; jj++) xv[jj] = sxk[(p0+jj)*36 + k];
            #pragma unroll
            for (int jj = 0; jj < 4; jj++) {
                acc[0][jj] = fmaf(g0, xv[jj], acc[0][jj]);
                acc[1][jj] = fmaf(g1, xv[jj], acc[1][jj]);
            }
        }
        #pragma unroll
        for (int qi = 0; qi < 2; qi++) {
            int q = q0 + qi;
            float sq = ss[64+q];
            #pragma unroll
            for (int jj = 0; jj < 4; jj++) {
                int p = p0 + jj;
                float av = scale * (ss[p] + sq - 2.f*acc[qi][jj]);
                if (A[(64 + q)*80 + p] == 0.f) av = -INFINITY;
                sal[q*64 + p] = av;
            }
        }
    }
    __syncthreads();
    const int lane = tid & 31, w = tid >> 5;
    for (int q = w; q < 16; q += 8) {
        float a0 = sal[q*64 + lane], a1 = sal[q*64 + 32 + lane];
        float mx = fmaxf(a0, a1);
        #pragma unroll
        for (int off = 16; off; off >>= 1) mx = fmaxf(mx, __shfl_xor_sync(0xffffffffu, mx, off));
        float e0 = expf(a0 - mx), e1 = expf(a1 - mx);
        float se = e0 + e1;
        float sy = e0*syk[lane] + e1*syk[32 + lane];
        #pragma unroll
        for (int off = 16; off; off >>= 1) {
            se += __shfl_xor_sync(0xffffffffu, se, off);
            sy += __shfl_xor_sync(0xffffffffu, sy, off);
        }
        if (lane == 0) syh[q] = sy / se;
    }
    __syncthreads();
    for (int i = tid; i < 16*36; i += NT) {
        int q = i / 36, c = i - q*36;
        float v = (c < 34) ? sxk[(64 + q)*36 + c] : ((c == 34) ? syh[q] : 0.f);
        x2n[(size_t)(b*16 + q)*36 + c] = v;
    }
}

// ---------------- cd: pairwise distances (inputs stride 36) --------------------------
__global__ void cd_kernel(const float* __restrict__ x /*stride 36*/,
                          const float* __restrict__ x2n /*stride 36*/,
                          float* __restrict__ cd)
{
    __shared__ float sxa[80*35];
    __shared__ float ssq[80];
    const int b = blockIdx.x, tid = threadIdx.x;
    for (int i = tid; i < 80*35; i += blockDim.x) {
        int n = i / 35, c = i - n*35;
        sxa[i] = (n < 64) ? x[(size_t)(b*64 + n)*36 + c]
                          : x2n[(size_t)(b*16 + (n - 64))*36 + c];
    }
    __syncthreads();
    if (tid < 80) {
        float s = 0.f;
        #pragma unroll 5
        for (int c = 0; c < 35; c++) { float v = sxa[tid*35 + c]; s = fmaf(v, v, s); }
        ssq[tid] = s;
    }
    __syncthreads();
    const int tr = tid >> 4, tc = tid & 15;
    float acc[5][5];
    #pragma unroll
    for (int i = 0; i < 5; i++)
        #pragma unroll
        for (int j = 0; j < 5; j++) acc[i][j] = 0.f;
    for (int k = 0; k < 35; k++) {
        float rv[5], cv[5];
        #pragma unroll
        for (int i = 0; i < 5; i++) rv[i] = sxa[(tr + 16*i)*35 + k];
        #pragma unroll
        for (int j = 0; j < 5; j++) cv[j] = sxa[(tc + 16*j)*35 + k];
        #pragma unroll
        for (int i = 0; i < 5; i++)
            #pragma unroll
            for (int j = 0; j < 5; j++) acc[i][j] = fmaf(rv[i], cv[j], acc[i][j]);
    }
    float* out = cd + (size_t)b*6400;
    #pragma unroll
    for (int i = 0; i < 5; i++) {
        int r = tr + 16*i;
        float sr = ssq[r];
        #pragma unroll
        for (int j = 0; j < 5; j++) {
            int c = tc + 16*j;
            float d2 = sr + ssq[c] - 2.f*acc[i][j];
            out[r*80 + c] = sqrtf(fmaxf(d2, 0.f));
        }
    }
}

// ====================================================================================
extern "C" void kernel_launch(void* const* d_in, const int* in_sizes, int n_in,
                              void* d_out, int out_size)
{
    const int*   x1_cat   = (const int*)  d_in[0];
    const float* x1_num   = (const float*)d_in[1];
    const int*   x2_cat   = (const int*)  d_in[2];
    const float* x2_num   = (const float*)d_in[3];
    const int*   e1       = (const int*)  d_in[4];
    const int*   e2       = (const int*)  d_in[5];
    const float* emb0     = (const float*)d_in[6];
    const float* emb1     = (const float*)d_in[7];
    const float* emb2     = (const float*)d_in[8];
    const float* pre_W1   = (const float*)d_in[9];
    const float* pre_b1   = (const float*)d_in[10];
    const float* pre_W2   = (const float*)d_in[11];
    const float* pre_b2   = (const float*)d_in[12];
    const float* pre_W3   = (const float*)d_in[13];
    const float* pre_b3   = (const float*)d_in[14];
    const float* g1_W1    = (const float*)d_in[15];
    const float* g1_b1    = (const float*)d_in[16];
    const float* g1_W2    = (const float*)d_in[17];
    const float* g1_b2    = (const float*)d_in[18];
    const float* g2_W1    = (const float*)d_in[19];
    const float* g2_b1    = (const float*)d_in[20];
    const float* g2_W2    = (const float*)d_in[21];
    const float* g2_b2    = (const float*)d_in[22];
    const float* ker_W    = (const float*)d_in[23];
    const float* smoothing= (const float*)d_in[24];
    const float* Mmat     = (const float*)d_in[25];

    const int n1 = in_sizes[0] / 3;
    const int n2 = in_sizes[2] / 3;
    const int E1 = in_sizes[4] / 2;
    const int E2 = in_sizes[5] / 2;
    const int* e1src = e1, *e1dst = e1 + E1;
    const int* e2src = e2, *e2dst = e2 + E2;

    float* out   = (float*)d_out;
    float* outO  = out;
    float* outCD = out + 32768;
    float* outA  = out + 32768 + 13107200;

    float *px, *px2p, *pA, *pC, *pd1, *pd2, *pth, *px2n;
    cudaGetSymbolAddress((void**)&px,   g_x);
    cudaGetSymbolAddress((void**)&px2p, g_x2p);
    cudaGetSymbolAddress((void**)&pA,   g_bufA);
    cudaGetSymbolAddress((void**)&pC,   g_bufC);
    cudaGetSymbolAddress((void**)&pd1,  g_dinv1);
    cudaGetSymbolAddress((void**)&pd2,  g_dinv2);
    cudaGetSymbolAddress((void**)&pth,  g_theta);
    cudaGetSymbolAddress((void**)&px2n, g_x2n);
    int *pcnt1, *prp1, *pcur1, *pei1, *pcnt2, *prp2, *pcur2, *pei2, *ppart;
    cudaGetSymbolAddress((void**)&pcnt1, g_counts1);
    cudaGetSymbolAddress((void**)&prp1,  g_rowptr1);
    cudaGetSymbolAddress((void**)&pcur1, g_cursor1);
    cudaGetSymbolAddress((void**)&pei1,  g_eidx1);
    cudaGetSymbolAddress((void**)&pcnt2, g_counts2);
    cudaGetSymbolAddress((void**)&prp2,  g_rowptr2);
    cudaGetSymbolAddress((void**)&pcur2, g_cursor2);
    cudaGetSymbolAddress((void**)&pei2,  g_eidx2);
    cudaGetSymbolAddress((void**)&ppart, g_partials);

    static cudaStream_t s1 = 0, s2 = 0;
    static cudaEvent_t evFork = 0, evJoin1 = 0, evPre2 = 0, evAlpha = 0, evCd = 0;
    if (!s1) {
        cudaStreamCreateWithFlags(&s1, cudaStreamNonBlocking);
        cudaStreamCreateWithFlags(&s2, cudaStreamNonBlocking);
        cudaEventCreateWithFlags(&evFork,  cudaEventDisableTiming);
        cudaEventCreateWithFlags(&evJoin1, cudaEventDisableTiming);
        cudaEventCreateWithFlags(&evPre2,  cudaEventDisableTiming);
        cudaEventCreateWithFlags(&evAlpha, cudaEventDisableTiming);
        cudaEventCreateWithFlags(&evCd,    cudaEventDisableTiming);
    }

    cudaEventRecord(evFork, 0);
    cudaStreamWaitEvent(s1, evFork, 0);
    cudaStreamWaitEvent(s2, evFork, 0);

    // ---- s1: misc + merged CSR build ----
    misc_kernel<<<1, 1024, 0, s1>>>(Mmat, outA, ker_W, pth);
    zero_both_kernel<<<256, 256, 0, s1>>>(pcnt1, n1, pcnt2, n2);
    count_both_kernel<<<(E1 + E2 + 255)/256, 256, 0, s1>>>(e1dst, E1, e2dst, E2, pcnt1, pcnt2);
    {
        int B1 = (n1 + 4095)/4096;
        int B2 = (n2 + 4095)/4096;
        scan1_both_kernel<<<B1 + B2, 1024, 0, s1>>>(pcnt1, prp1, n1, B1, pcnt2, prp2, n2, ppart);
        scan2_both_kernel<<<1, 64, 0, s1>>>(ppart, B1, B2);
        scan3_both_kernel<<<(n1 + n2 + 255)/256, 256, 0, s1>>>(
            prp1, pcnt1, pcur1, pd1, n1, prp2, pcnt2, pcur2, pd2, n2, ppart);
    }
    scatter_both_kernel<<<(E1 + E2 + 255)/256, 256, 0, s1>>>(
        e1src, e1dst, E1, pcur1, pei1, e2src, e2dst, E2, pcur2, pei2);
    cudaEventRecord(evJoin1, s1);

    // ---- s2: pre MLP for x2 ----
    const int smemPre = (35*128 + 128*128 + 128*34 + 128 + 128 + 48) * 4;
    cudaFuncSetAttribute(pre_kernel, cudaFuncAttributeMaxDynamicSharedMemorySize, smemPre);
    pre_kernel<<<64, 256, smemPre, s2>>>(x2_cat, x2_num, n2,
        pre_W1, pre_b1, pre_W2, pre_b2, pre_W3, pre_b3, emb0, emb1, emb2, px2p);
    cudaEventRecord(evPre2, s2);

    // ---- main: pre MLP x1 ----
    pre_kernel<<<296, 256, smemPre>>>(x1_cat, x1_num, n1,
        pre_W1, pre_b1, pre_W2, pre_b2, pre_W3, pre_b3, emb0, emb1, emb2, px);

    cudaStreamWaitEvent(0, evJoin1, 0);

    // GCN1: fused gather+W1+relu+W2 -> hw2 (stride 36), then aggregate + bias
    gather_mm35_w2_kernel<<<(n1 + 15)/16, 512>>>(px, prp1, pcnt1, pei1, pd1,
                                                 g1_W1, g1_b1, g1_W2, 34, pA, n1);
    gather34_kernel<<<(n1 + 15)/16, 512>>>(pA, prp1, pcnt1, pei1, pd1, g1_b2, pC, n1);

    // alpha (produces x2n)
    cudaStreamWaitEvent(0, evPre2, 0);
    alpha_kernel<<<SBK, 256>>>(pC, px2p, px, pth, outA, smoothing, px2n);
    cudaEventRecord(evAlpha, 0);

    // ---- s2: cd overlaps GCN2 chain ----
    cudaStreamWaitEvent(s2, evAlpha, 0);
    cd_kernel<<<SBK, 256, 0, s2>>>(px, px2n, outCD);
    cudaEventRecord(evCd, s2);

    // GCN2 on main stream
    gather_mm35_w2_kernel<<<(n2 + 15)/16, 512>>>(px2n, prp2, pcnt2, pei2, pd2,
                                                 g2_W1, g2_b1, g2_W2, 1, pA, n2);
    gather1_kernel<<<(n2 + 255)/256, 256>>>(pA, prp2, pcnt2, pei2, pd2, g2_b2, outO, n2);

    cudaStreamWaitEvent(0, evCd, 0);
}

// round 16
// speedup vs baseline: 1.5709x; 1.5709x over previous
#include <cuda_runtime.h>
#include <math.h>

#define SBK   2048
#define PASTK 64
#define FUTK  16
#define N1K   (SBK*PASTK)
#define N2K   (SBK*FUTK)
#define E1K   (N1K*8)
#define E2K   (N2K*8)

// ---------------- device scratch -------------------------------------------------
__device__ float g_x[N1K*35];
__device__ float g_x2p[N2K*35];
__device__ float g_bufA[N1K*64];
__device__ float g_bufC[N1K*64];
__device__ float g_dinv1[N1K];
__device__ float g_dinv2[N2K];
__device__ float g_theta[34*34];
__device__ float g_x2n[N2K*35];
__device__ int g_counts1[N1K];
__device__ int g_rowptr1[N1K];
__device__ int g_cursor1[N1K];
__device__ int g_eidx1[E1K];
__device__ int g_counts2[N2K];
__device__ int g_rowptr2[N2K];
__device__ int g_cursor2[N2K];
__device__ int g_eidx2[E2K];
__device__ int g_partials[128];

// ---------------- misc: A + theta ---------------------------------------------------
__global__ void misc_kernel(const float* __restrict__ M, float* __restrict__ A,
                            const float* __restrict__ kerW, float* __restrict__ th)
{
    __shared__ float sM[80*26];
    int tid = threadIdx.x;
    for (int i = tid; i < 80*26; i += blockDim.x) sM[i] = M[i];
    __syncthreads();
    for (int idx = tid; idx < 34*34; idx += blockDim.x) {
        int i = idx / 34, j = idx - i*34;
        float s = 0.f;
        #pragma unroll 8
        for (int k = 0; k < 128; k++) s = fmaf(kerW[i*128+k], kerW[j*128+k], s);
        th[idx] = s;
    }
    if (tid < 80) {
        int i = tid;
        float mx = -INFINITY;
        for (int j = 0; j <= i; j++) {
            float s = 0.f;
            #pragma unroll
            for (int k = 0; k < 26; k++) s = fmaf(sM[i*26+k], sM[j*26+k], s);
            s = fmaxf(s, 0.f);
            mx = fmaxf(mx, s);
        }
        float sum = 0.f;
        for (int j = 0; j <= i; j++) {
            float s = 0.f;
            #pragma unroll
            for (int k = 0; k < 26; k++) s = fmaf(sM[i*26+k], sM[j*26+k], s);
            s = fmaxf(s, 0.f);
            float e = expf(s - mx);
            sum += e;
            A[i*80+j] = e;
        }
        float inv = 1.f / sum;
        for (int j = 0; j <= i; j++) A[i*80+j] *= inv;
        for (int j = i+1; j < 80; j++) A[i*80+j] = 0.f;
    }
}

// ---------------- pre MLP: 8 rows/warp --------------------------------------------
__global__ void __launch_bounds__(256, 2)
pre_kernel(const int* __restrict__ cat, const float* __restrict__ num, int nrows,
           const float* __restrict__ W1, const float* __restrict__ b1,
           const float* __restrict__ W2, const float* __restrict__ b2,
           const float* __restrict__ W3, const float* __restrict__ b3,
           const float* __restrict__ emb0, const float* __restrict__ emb1,
           const float* __restrict__ emb2, float* __restrict__ out)
{
    extern __shared__ float smem[];
    float* sW1 = smem;
    float* sW2 = sW1 + 35*128;
    float* sW3 = sW2 + 128*128;
    float* sb1 = sW3 + 128*34;
    float* sb2 = sb1 + 128;
    float* sb3 = sb2 + 128;
    int tid = threadIdx.x;
    for (int i = tid; i < 35*128;  i += blockDim.x) sW1[i] = W1[i];
    for (int i = tid; i < 128*128; i += blockDim.x) sW2[i] = W2[i];
    for (int i = tid; i < 128*34;  i += blockDim.x) sW3[i] = W3[i];
    if (tid < 128) { sb1[tid] = b1[tid]; sb2[tid] = b2[tid]; }
    if (tid < 34) sb3[tid] = b3[tid];
    __syncthreads();
    const int lane = tid & 31, warp = tid >> 5, nw = blockDim.x >> 5;
    const unsigned FULL = 0xffffffffu;
    const int R = 8;
    const int rstep = gridDim.x*nw*R;
    for (int r0 = (blockIdx.x*nw + warp)*R; r0 < nrows; r0 += rstep) {
        float oa[R], ob[R];
        #pragma unroll
        for (int j = 0; j < R; j++) {
            int r = min(r0 + j, nrows - 1);
            int c0 = cat[3*r], c1 = cat[3*r+1], c2 = cat[3*r+2];
            float v;
            if (lane < 16)      v = emb0[c0*16 + lane];
            else if (lane < 24) v = emb1[c1*8 + lane - 16];
            else                v = emb2[c2*8 + lane - 24];
            oa[j] = v;
            ob[j] = (lane < 3) ? num[3*r + lane] : 0.f;
        }
        float4 a[R];
        {
            float4 bias = ((const float4*)sb1)[lane];
            #pragma unroll
            for (int j = 0; j < R; j++) a[j] = bias;
            #pragma unroll
            for (int k = 0; k < 35; k++) {
                float4 w = ((const float4*)(sW1 + k*128))[lane];
                #pragma unroll
                for (int j = 0; j < R; j++) {
                    float xv = (k < 32) ? __shfl_sync(FULL, oa[j], k)
                                        : __shfl_sync(FULL, ob[j], k - 32);
                    a[j].x = fmaf(xv, w.x, a[j].x); a[j].y = fmaf(xv, w.y, a[j].y);
                    a[j].z = fmaf(xv, w.z, a[j].z); a[j].w = fmaf(xv, w.w, a[j].w);
                }
            }
            #pragma unroll
            for (int j = 0; j < R; j++) {
                a[j].x = fmaxf(a[j].x,0.f); a[j].y = fmaxf(a[j].y,0.f);
                a[j].z = fmaxf(a[j].z,0.f); a[j].w = fmaxf(a[j].w,0.f);
            }
        }
        float4 bb[R];
        {
            float4 bias = ((const float4*)sb2)[lane];
            #pragma unroll
            for (int j = 0; j < R; j++) bb[j] = bias;
            #pragma unroll 4
            for (int k = 0; k < 128; k++) {
                float4 w = ((const float4*)(sW2 + k*128))[lane];
                const int srcl = k >> 2;
                #pragma unroll
                for (int j = 0; j < R; j++) {
                    float comp = ((k & 3) == 0) ? a[j].x : ((k & 3) == 1) ? a[j].y
                               : ((k & 3) == 2) ? a[j].z : a[j].w;
                    float hv = __shfl_sync(FULL, comp, srcl);
                    bb[j].x = fmaf(hv, w.x, bb[j].x); bb[j].y = fmaf(hv, w.y, bb[j].y);
                    bb[j].z = fmaf(hv, w.z, bb[j].z); bb[j].w = fmaf(hv, w.w, bb[j].w);
                }
            }
            #pragma unroll
            for (int j = 0; j < R; j++) {
                bb[j].x = fmaxf(bb[j].x,0.f); bb[j].y = fmaxf(bb[j].y,0.f);
                bb[j].z = fmaxf(bb[j].z,0.f); bb[j].w = fmaxf(bb[j].w,0.f);
            }
        }
        {
            const int j0 = lane, j1 = lane + 32;
            const bool has1 = (j1 < 34);
            float acc0[R], acc1[R];
            #pragma unroll
            for (int j = 0; j < R; j++) { acc0[j] = 0.f; acc1[j] = 0.f; }
            #pragma unroll 4
            for (int k = 0; k < 128; k++) {
                float w0 = sW3[k*34 + j0];
                float w1 = has1 ? sW3[k*34 + j1] : 0.f;
                const int srcl = k >> 2;
                #pragma unroll
                for (int j = 0; j < R; j++) {
                    float comp = ((k & 3) == 0) ? bb[j].x : ((k & 3) == 1) ? bb[j].y
                               : ((k & 3) == 2) ? bb[j].z : bb[j].w;
                    float hv = __shfl_sync(FULL, comp, srcl);
                    acc0[j] = fmaf(hv, w0, acc0[j]);
                    acc1[j] = fmaf(hv, w1, acc1[j]);
                }
            }
            #pragma unroll
            for (int j = 0; j < R; j++) {
                int r = min(r0 + j, nrows - 1);
                float n2v = __shfl_sync(FULL, ob[j], 2);
                float* orow = out + (size_t)r*35;
                orow[j0] = acc0[j] + sb3[j0];
                if (has1) orow[j1] = acc1[j] + sb3[j1];
                if (lane == 0) orow[34] = n2v;
            }
        }
    }
}

// ---------------- merged CSR build ---------------------------------------------------
__global__ void zero_both_kernel(int* __restrict__ c1, int n1, int* __restrict__ c2, int n2)
{
    for (int i = blockIdx.x*blockDim.x + threadIdx.x; i < n1 + n2; i += gridDim.x*blockDim.x) {
        if (i < n1) c1[i] = 0; else c2[i - n1] = 0;
    }
}
__global__ void count_both_kernel(const int* __restrict__ d1, int E1,
                                  const int* __restrict__ d2, int E2,
                                  int* __restrict__ c1, int* __restrict__ c2)
{
    int e = blockIdx.x*blockDim.x + threadIdx.x;
    if (e < E1) atomicAdd(&c1[d1[e]], 1);
    else if (e - E1 < E2) atomicAdd(&c2[d2[e - E1]], 1);
}
__global__ void scan1_both_kernel(const int* __restrict__ in1, int* __restrict__ out1, int n1, int B1,
                                  const int* __restrict__ in2, int* __restrict__ out2, int n2,
                                  int* __restrict__ partials)
{
    __shared__ int sdata[1024];
    int tid = threadIdx.x;
    const int* in; int* outp; int n; int blk; int* part;
    if ((int)blockIdx.x < B1) { in = in1; outp = out1; n = n1; blk = blockIdx.x; part = partials; }
    else { in = in2; outp = out2; n = n2; blk = blockIdx.x - B1; part = partials + 64; }
    int base = blk*4096 + tid*4;
    int v[4];
    #pragma unroll
    for (int j = 0; j < 4; j++) v[j] = (base + j < n) ? in[base + j] : 0;
    int tsum = v[0] + v[1] + v[2] + v[3];
    sdata[tid] = tsum;
    __syncthreads();
    for (int off = 1; off < 1024; off <<= 1) {
        int add = (tid >= off) ? sdata[tid - off] : 0;
        __syncthreads();
        sdata[tid] += add;
        __syncthreads();
    }
    int run = sdata[tid] - tsum;
    #pragma unroll
    for (int j = 0; j < 4; j++) {
        if (base + j < n) outp[base + j] = run;
        run += v[j];
    }
    if (tid == 1023) part[blk] = sdata[1023];
}
__global__ void scan2_both_kernel(int* __restrict__ partials, int B1, int B2)
{
    int tid = threadIdx.x;
    int w = tid >> 5, lane = tid & 31;
    const unsigned FULL = 0xffffffffu;
    int* p = partials + (w ? 64 : 0);
    int B = w ? B2 : B1;
    if (w < 2) {
        int orig = (lane < B) ? p[lane] : 0;
        int v = orig;
        #pragma unroll
        for (int off = 1; off < 32; off <<= 1) {
            int t = __shfl_up_sync(FULL, v, off);
            if (lane >= off) v += t;
        }
        if (lane < B) p[lane] = v - orig;
    }
}
__global__ void scan3_both_kernel(int* __restrict__ rp1, const int* __restrict__ c1,
                                  int* __restrict__ cur1, float* __restrict__ dv1, int n1,
                                  int* __restrict__ rp2, const int* __restrict__ c2,
                                  int* __restrict__ cur2, float* __restrict__ dv2, int n2,
                                  const int* __restrict__ partials)
{
    int i = blockIdx.x*blockDim.x + threadIdx.x;
    if (i < n1) {
        int rp = rp1[i] + partials[i >> 12];
        rp1[i] = rp; cur1[i] = rp;
        dv1[i] = rsqrtf(1.0f + (float)c1[i]);
    } else if (i - n1 < n2) {
        int j = i - n1;
        int rp = rp2[j] + partials[64 + (j >> 12)];
        rp2[j] = rp; cur2[j] = rp;
        dv2[j] = rsqrtf(1.0f + (float)c2[j]);
    }
}
__global__ void scatter_both_kernel(const int* __restrict__ s1, const int* __restrict__ d1, int E1,
                                    int* __restrict__ cur1, int* __restrict__ ei1,
                                    const int* __restrict__ s2, const int* __restrict__ d2, int E2,
                                    int* __restrict__ cur2, int* __restrict__ ei2)
{
    int e = blockIdx.x*blockDim.x + threadIdx.x;
    if (e < E1) {
        int pos = atomicAdd(&cur1[d1[e]], 1);
        ei1[pos] = s1[e];
    } else if (e - E1 < E2) {
        int j = e - E1;
        int pos = atomicAdd(&cur2[d2[j]], 1);
        ei2[pos] = s2[j];
    }
}

// ---------------- fused GCN layer-1 + W2 (round-9 exact) ----------------------------
__global__ void __launch_bounds__(512)
gather_mm35_w2_kernel(const float* __restrict__ x /*stride 35*/,
                      const int* __restrict__ rowptr, const int* __restrict__ counts,
                      const int* __restrict__ eidx, const float* __restrict__ dinv,
                      const float* __restrict__ W1, const float* __restrict__ b1,
                      const float* __restrict__ W2, int dout2,
                      float* __restrict__ out, int n)
{
    __shared__ float sW1[35*64];
    __shared__ float sb1[64];
    __shared__ float sW2[64*34];
    int tid = threadIdx.x;
    for (int i = tid; i < 35*64; i += blockDim.x) sW1[i] = W1[i];
    if (tid < 64) sb1[tid] = b1[tid];
    for (int i = tid; i < 64*dout2; i += blockDim.x) sW2[i] = W2[i];
    __syncthreads();
    const unsigned FULL = 0xffffffffu;
    int gw = (blockIdx.x*blockDim.x + tid) >> 5;
    int lane = tid & 31;
    if (gw >= n) return;
    const int r = gw;
    const int j0 = lane, j1 = lane + 32;
    const bool has1 = (j1 < 35);
    float dr = dinv[r];
    float d2 = dr*dr;
    const float* hr = x + (size_t)r*35;
    float a0 = __ldg(&hr[j0])*d2;
    float a1 = has1 ? __ldg(&hr[j1])*d2 : 0.f;
    float b0 = 0.f, bx1 = 0.f, c0 = 0.f, c1 = 0.f, e0 = 0.f, e1 = 0.f;
    int start = rowptr[r], cnt = counts[r];
    int i = 0;
    for (; i + 4 <= cnt; i += 4) {
        int s0 = __ldg(&eidx[start+i]);
        int s1 = __ldg(&eidx[start+i+1]);
        int s2 = __ldg(&eidx[start+i+2]);
        int s3 = __ldg(&eidx[start+i+3]);
        float f0 = __ldg(&dinv[s0])*dr;
        float f1 = __ldg(&dinv[s1])*dr;
        float f2 = __ldg(&dinv[s2])*dr;
        float f3 = __ldg(&dinv[s3])*dr;
        const float* p0 = x + (size_t)s0*35;
        const float* p1 = x + (size_t)s1*35;
        const float* p2 = x + (size_t)s2*35;
        const float* p3 = x + (size_t)s3*35;
        a0 = fmaf(f0, __ldg(&p0[j0]), a0);
        b0 = fmaf(f1, __ldg(&p1[j0]), b0);
        c0 = fmaf(f2, __ldg(&p2[j0]), c0);
        e0 = fmaf(f3, __ldg(&p3[j0]), e0);
        if (has1) {
            a1  = fmaf(f0, __ldg(&p0[j1]), a1);
            bx1 = fmaf(f1, __ldg(&p1[j1]), bx1);
            c1  = fmaf(f2, __ldg(&p2[j1]), c1);
            e1  = fmaf(f3, __ldg(&p3[j1]), e1);
        }
    }
    for (; i < cnt; i++) {
        int s = __ldg(&eidx[start+i]);
        float f = __ldg(&dinv[s])*dr;
        const float* p = x + (size_t)s*35;
        a0 = fmaf(f, __ldg(&p[j0]), a0);
        if (has1) a1 = fmaf(f, __ldg(&p[j1]), a1);
    }
    a0 += b0 + c0 + e0;
    a1 += bx1 + c1 + e1;
    float o0 = sb1[lane], o1 = sb1[lane + 32];
    #pragma unroll
    for (int k = 0; k < 35; k++) {
        float xv = (k < 32) ? __shfl_sync(FULL, a0, k)
                            : __shfl_sync(FULL, a1, k - 32);
        o0 = fmaf(xv, sW1[k*64 + lane], o0);
        o1 = fmaf(xv, sW1[k*64 + 32 + lane], o1);
    }
    o0 = fmaxf(o0, 0.f); o1 = fmaxf(o1, 0.f);
    if (dout2 == 34) {
        const bool hasHi = (lane < 2);
        float z0 = 0.f, z1 = 0.f;
        #pragma unroll 8
        for (int k = 0; k < 64; k++) {
            float hv = (k < 32) ? __shfl_sync(FULL, o0, k)
                                : __shfl_sync(FULL, o1, k - 32);
            z0 = fmaf(hv, sW2[k*34 + lane], z0);
            if (hasHi) z1 = fmaf(hv, sW2[k*34 + 32 + lane], z1);
        }
        float* orow = out + (size_t)r*36;
        orow[lane] = z0;
        if (hasHi) orow[lane + 32] = z1;
    } else {
        float z = o0*sW2[lane] + o1*sW2[lane + 32];
        #pragma unroll
        for (int off = 16; off; off >>= 1) z += __shfl_xor_sync(FULL, z, off);
        if (lane == 0) out[r] = z;
    }
}

// ---------------- GCN gather (round-9 exact) ----------------------------------------
__global__ void __launch_bounds__(512)
gather_kernel(const float* __restrict__ h, int stride, int dout,
              const int* __restrict__ rowptr, const int* __restrict__ counts,
              const int* __restrict__ eidx, const float* __restrict__ dinv,
              const float* __restrict__ bias, float* __restrict__ out,
              int outStride, int n, int doRelu)
{
    int gw = (blockIdx.x*blockDim.x + threadIdx.x) >> 5;
    int lane = threadIdx.x & 31;
    if (gw >= n) return;
    const int r = gw;
    const int j0 = lane, j1 = lane + 32;
    const bool has1 = (j1 < dout);
    float dr = dinv[r];
    float d2 = dr*dr;
    const float* hr = h + (size_t)r*stride;
    float a0 = __ldg(&hr[j0])*d2;
    float a1 = has1 ? __ldg(&hr[j1])*d2 : 0.f;
    float b0 = 0.f, b1 = 0.f, c0 = 0.f, c1 = 0.f, e0 = 0.f, e1 = 0.f;
    int start = rowptr[r], cnt = counts[r];
    int i = 0;
    for (; i + 4 <= cnt; i += 4) {
        int s0 = __ldg(&eidx[start+i]);
        int s1 = __ldg(&eidx[start+i+1]);
        int s2 = __ldg(&eidx[start+i+2]);
        int s3 = __ldg(&eidx[start+i+3]);
        float f0 = __ldg(&dinv[s0])*dr;
        float f1 = __ldg(&dinv[s1])*dr;
        float f2 = __ldg(&dinv[s2])*dr;
        float f3 = __ldg(&dinv[s3])*dr;
        const float* p0 = h + (size_t)s0*stride;
        const float* p1 = h + (size_t)s1*stride;
        const float* p2 = h + (size_t)s2*stride;
        const float* p3 = h + (size_t)s3*stride;
        a0 = fmaf(f0, __ldg(&p0[j0]), a0);
        b0 = fmaf(f1, __ldg(&p1[j0]), b0);
        c0 = fmaf(f2, __ldg(&p2[j0]), c0);
        e0 = fmaf(f3, __ldg(&p3[j0]), e0);
        if (has1) {
            a1 = fmaf(f0, __ldg(&p0[j1]), a1);
            b1 = fmaf(f1, __ldg(&p1[j1]), b1);
            c1 = fmaf(f2, __ldg(&p2[j1]), c1);
            e1 = fmaf(f3, __ldg(&p3[j1]), e1);
        }
    }
    for (; i < cnt; i++) {
        int s = __ldg(&eidx[start+i]);
        float f = __ldg(&dinv[s])*dr;
        const float* p = h + (size_t)s*stride;
        a0 = fmaf(f, __ldg(&p[j0]), a0);
        if (has1) a1 = fmaf(f, __ldg(&p[j1]), a1);
    }
    a0 += b0 + c0 + e0;
    if (bias) a0 += bias[j0];
    if (doRelu) a0 = fmaxf(a0, 0.f);
    float* orow = out + (size_t)r*outStride;
    orow[j0] = a0;
    if (has1) {
        a1 += b1 + c1 + e1;
        if (bias) a1 += bias[j1];
        if (doRelu) a1 = fmaxf(a1, 0.f);
        orow[j1] = a1;
    }
}

__global__ void gather1_kernel(const float* __restrict__ h,
                               const int* __restrict__ rowptr, const int* __restrict__ counts,
                               const int* __restrict__ eidx, const float* __restrict__ dinv,
                               const float* __restrict__ bias, float* __restrict__ out, int n)
{
    int r = blockIdx.x*blockDim.x + threadIdx.x;
    if (r >= n) return;
    float dr = dinv[r];
    float a = h[r]*dr*dr, b = 0.f, c = 0.f, e = 0.f;
    int start = rowptr[r], cnt = counts[r];
    int i = 0;
    for (; i + 4 <= cnt; i += 4) {
        int s0 = __ldg(&eidx[start+i]);
        int s1 = __ldg(&eidx[start+i+1]);
        int s2 = __ldg(&eidx[start+i+2]);
        int s3 = __ldg(&eidx[start+i+3]);
        a = fmaf(__ldg(&dinv[s0])*dr, __ldg(&h[s0]), a);
        b = fmaf(__ldg(&dinv[s1])*dr, __ldg(&h[s1]), b);
        c = fmaf(__ldg(&dinv[s2])*dr, __ldg(&h[s2]), c);
        e = fmaf(__ldg(&dinv[s3])*dr, __ldg(&h[s3]), e);
    }
    for (; i < cnt; i++) {
        int s = __ldg(&eidx[start+i]);
        a = fmaf(__ldg(&dinv[s])*dr, __ldg(&h[s]), a);
    }
    out[r] = a + b + c + e + bias[0];
}

// ---------------- alpha (register-tiled, no cd) --------------------------------------
__global__ void __launch_bounds__(256)
alpha_kernel(const float* __restrict__ x1g /*stride 36*/,
             const float* __restrict__ x2p /*stride 35*/,
             const float* __restrict__ xfull /*stride 35*/,
             const float* __restrict__ theta,
             const float* __restrict__ A,
             const float* __restrict__ smoothing,
             float* __restrict__ x2n)
{
    __shared__ float sxk[80*36];
    __shared__ float sth[34*34];
    __shared__ float sG[80*36];
    __shared__ float ss[80];
    __shared__ float syk[64];
    __shared__ float sal[16*64];
    __shared__ float syh[16];
    const int b = blockIdx.x, tid = threadIdx.x;
    const int NT = 256;
    for (int i = tid; i < 34*34; i += NT) sth[i] = theta[i];
    for (int i = tid; i < 80*34; i += NT) {
        int n = i / 34, o = i - n*34;
        float v = (n < 64) ? x1g[(size_t)(b*64 + n)*36 + o]
                           : x2p[(size_t)(b*16 + (n - 64))*35 + o];
        sxk[n*36 + o] = v;
    }
    if (tid < 64) syk[tid] = xfull[(size_t)(b*64 + tid)*35 + 34];
    __syncthreads();
    for (int t = tid; t < 180; t += NT) {
        int ng = t / 9, og = t - ng*9;
        int n0 = ng*4, o0 = og*4;
        float acc[4][4];
        #pragma unroll
        for (int ii = 0; ii < 4; ii++)
            #pragma unroll
            for (int jj = 0; jj < 4; jj++) acc[ii][jj] = 0.f;
        #pragma unroll 2
        for (int k = 0; k < 34; k++) {
            float wv[4], xv[4];
            #pragma unroll
            for (int ii = 0; ii < 4; ii++) wv[ii] = sth[min(o0+ii,33)*34 + k];
            #pragma unroll
            for (int jj = 0; jj < 4; jj++) xv[jj] = sxk[(n0+jj)*36 + k];
            #pragma unroll
            for (int ii = 0; ii < 4; ii++)
                #pragma unroll
                for (int jj = 0; jj < 4; jj++) acc[ii][jj] = fmaf(wv[ii], xv[jj], acc[ii][jj]);
        }
        #pragma unroll
        for (int ii = 0; ii < 4; ii++) {
            if (o0 + ii < 34)
                #pragma unroll
                for (int jj = 0; jj < 4; jj++) sG[(n0+jj)*36 + o0 + ii] = acc[ii][jj];
        }
    }
    __syncthreads();
    for (int nn = tid; nn < 80; nn += NT) {
        float s = 0.f;
        #pragma unroll 2
        for (int k = 0; k < 34; k++) s = fmaf(sG[nn*36+k], sxk[nn*36+k], s);
        ss[nn] = s;
    }
    __syncthreads();
    float sm0 = smoothing[0];
    float sig = 1.f / (1.f + expf(-sm0));
    float scale = -0.5f / (sig * 0.01f);
    if (tid < 128) {
        int qg = tid >> 4, pg = tid & 15;
        int q0 = qg*2, p0 = pg*4;
        float acc[2][4];
        #pragma unroll
        for (int qi = 0; qi < 2; qi++)
            #pragma unroll
            for (int jj = 0; jj < 4; jj++) acc[qi][jj] = 0.f;
        const float* gq0 = sG + (64+q0)*36;
        const float* gq1 = sG + (64+q0+1)*36;
        #pragma unroll 2
        for (int k = 0; k < 34; k++) {
            float g0 = gq0[k], g1 = gq1[k];
            float xv[4];
            #pragma unroll
            for (int jj = 0; jj < 4; jj++) xv[jj] = sxk[(p0+jj)*36 + k];
            #pragma unroll
            for (int jj = 0; jj < 4; jj++) {
                acc[0][jj] = fmaf(g0, xv[jj], acc[0][jj]);
                acc[1][jj] = fmaf(g1, xv[jj], acc[1][jj]);
            }
        }
        #pragma unroll
        for (int qi = 0; qi < 2; qi++) {
            int q = q0 + qi;
            float sq = ss[64+q];
            #pragma unroll
            for (int jj = 0; jj < 4; jj++) {
                int p = p0 + jj;
                float av = scale * (ss[p] + sq - 2.f*acc[qi][jj]);
                if (A[(64 + q)*80 + p] == 0.f) av = -INFINITY;
                sal[q*64 + p] = av;
            }
        }
    }
    __syncthreads();
    const int lane = tid & 31, w = tid >> 5;
    for (int q = w; q < 16; q += 8) {
        float a0 = sal[q*64 + lane], a1 = sal[q*64 + 32 + lane];
        float mx = fmaxf(a0, a1);
        #pragma unroll
        for (int off = 16; off; off >>= 1) mx = fmaxf(mx, __shfl_xor_sync(0xffffffffu, mx, off));
        float e0 = expf(a0 - mx), e1 = expf(a1 - mx);
        float se = e0 + e1;
        float sy = e0*syk[lane] + e1*syk[32 + lane];
        #pragma unroll
        for (int off = 16; off; off >>= 1) {
            se += __shfl_xor_sync(0xffffffffu, se, off);
            sy += __shfl_xor_sync(0xffffffffu, sy, off);
        }
        if (lane == 0) syh[q] = sy / se;
    }
    __syncthreads();
    for (int i = tid; i < 16*35; i += NT) {
        int q = i / 35, c = i - q*35;
        float v = (c < 34) ? sxk[(64 + q)*36 + c] : syh[q];
        x2n[(size_t)(b*16 + q)*35 + c] = v;
    }
}

// ---------------- cd: pairwise distances, 5x5 register tile --------------------------
__global__ void cd_kernel(const float* __restrict__ x, const float* __restrict__ x2n,
                          float* __restrict__ cd)
{
    __shared__ float sxa[80*35];
    __shared__ float ssq[80];
    const int b = blockIdx.x, tid = threadIdx.x;
    for (int i = tid; i < 80*35; i += blockDim.x) {
        int n = i / 35, c = i - n*35;
        sxa[i] = (n < 64) ? x[(size_t)(b*64 + n)*35 + c]
                          : x2n[(size_t)(b*16 + (n - 64))*35 + c];
    }
    __syncthreads();
    if (tid < 80) {
        float s = 0.f;
        #pragma unroll 5
        for (int c = 0; c < 35; c++) { float v = sxa[tid*35 + c]; s = fmaf(v, v, s); }
        ssq[tid] = s;
    }
    __syncthreads();
    const int tr = tid >> 4, tc = tid & 15;
    float acc[5][5];
    #pragma unroll
    for (int i = 0; i < 5; i++)
        #pragma unroll
        for (int j = 0; j < 5; j++) acc[i][j] = 0.f;
    for (int k = 0; k < 35; k++) {
        float rv[5], cv[5];
        #pragma unroll
        for (int i = 0; i < 5; i++) rv[i] = sxa[(tr + 16*i)*35 + k];
        #pragma unroll
        for (int j = 0; j < 5; j++) cv[j] = sxa[(tc + 16*j)*35 + k];
        #pragma unroll
        for (int i = 0; i < 5; i++)
            #pragma unroll
            for (int j = 0; j < 5; j++) acc[i][j] = fmaf(rv[i], cv[j], acc[i][j]);
    }
    float* out = cd + (size_t)b*6400;
    #pragma unroll
    for (int i = 0; i < 5; i++) {
        int r = tr + 16*i;
        float sr = ssq[r];
        #pragma unroll
        for (int j = 0; j < 5; j++) {
            int c = tc + 16*j;
            float d2 = sr + ssq[c] - 2.f*acc[i][j];
            out[r*80 + c] = sqrtf(fmaxf(d2, 0.f));
        }
    }
}

// ====================================================================================
extern "C" void kernel_launch(void* const* d_in, const int* in_sizes, int n_in,
                              void* d_out, int out_size)
{
    const int*   x1_cat   = (const int*)  d_in[0];
    const float* x1_num   = (const float*)d_in[1];
    const int*   x2_cat   = (const int*)  d_in[2];
    const float* x2_num   = (const float*)d_in[3];
    const int*   e1       = (const int*)  d_in[4];
    const int*   e2       = (const int*)  d_in[5];
    const float* emb0     = (const float*)d_in[6];
    const float* emb1     = (const float*)d_in[7];
    const float* emb2     = (const float*)d_in[8];
    const float* pre_W1   = (const float*)d_in[9];
    const float* pre_b1   = (const float*)d_in[10];
    const float* pre_W2   = (const float*)d_in[11];
    const float* pre_b2   = (const float*)d_in[12];
    const float* pre_W3   = (const float*)d_in[13];
    const float* pre_b3   = (const float*)d_in[14];
    const float* g1_W1    = (const float*)d_in[15];
    const float* g1_b1    = (const float*)d_in[16];
    const float* g1_W2    = (const float*)d_in[17];
    const float* g1_b2    = (const float*)d_in[18];
    const float* g2_W1    = (const float*)d_in[19];
    const float* g2_b1    = (const float*)d_in[20];
    const float* g2_W2    = (const float*)d_in[21];
    const float* g2_b2    = (const float*)d_in[22];
    const float* ker_W    = (const float*)d_in[23];
    const float* smoothing= (const float*)d_in[24];
    const float* Mmat     = (const float*)d_in[25];

    const int n1 = in_sizes[0] / 3;
    const int n2 = in_sizes[2] / 3;
    const int E1 = in_sizes[4] / 2;
    const int E2 = in_sizes[5] / 2;
    const int* e1src = e1, *e1dst = e1 + E1;
    const int* e2src = e2, *e2dst = e2 + E2;

    float* out   = (float*)d_out;
    float* outO  = out;
    float* outCD = out + 32768;
    float* outA  = out + 32768 + 13107200;

    float *px, *px2p, *pA, *pC, *pd1, *pd2, *pth, *px2n;
    cudaGetSymbolAddress((void**)&px,   g_x);
    cudaGetSymbolAddress((void**)&px2p, g_x2p);
    cudaGetSymbolAddress((void**)&pA,   g_bufA);
    cudaGetSymbolAddress((void**)&pC,   g_bufC);
    cudaGetSymbolAddress((void**)&pd1,  g_dinv1);
    cudaGetSymbolAddress((void**)&pd2,  g_dinv2);
    cudaGetSymbolAddress((void**)&pth,  g_theta);
    cudaGetSymbolAddress((void**)&px2n, g_x2n);
    int *pcnt1, *prp1, *pcur1, *pei1, *pcnt2, *prp2, *pcur2, *pei2, *ppart;
    cudaGetSymbolAddress((void**)&pcnt1, g_counts1);
    cudaGetSymbolAddress((void**)&prp1,  g_rowptr1);
    cudaGetSymbolAddress((void**)&pcur1, g_cursor1);
    cudaGetSymbolAddress((void**)&pei1,  g_eidx1);
    cudaGetSymbolAddress((void**)&pcnt2, g_counts2);
    cudaGetSymbolAddress((void**)&prp2,  g_rowptr2);
    cudaGetSymbolAddress((void**)&pcur2, g_cursor2);
    cudaGetSymbolAddress((void**)&pei2,  g_eidx2);
    cudaGetSymbolAddress((void**)&ppart, g_partials);

    static cudaStream_t s1 = 0, s2 = 0;
    static cudaEvent_t evFork = 0, evJoin1 = 0, evPre2 = 0, evAlpha = 0, evCd = 0;
    if (!s1) {
        cudaStreamCreateWithFlags(&s1, cudaStreamNonBlocking);
        cudaStreamCreateWithFlags(&s2, cudaStreamNonBlocking);
        cudaEventCreateWithFlags(&evFork,  cudaEventDisableTiming);
        cudaEventCreateWithFlags(&evJoin1, cudaEventDisableTiming);
        cudaEventCreateWithFlags(&evPre2,  cudaEventDisableTiming);
        cudaEventCreateWithFlags(&evAlpha, cudaEventDisableTiming);
        cudaEventCreateWithFlags(&evCd,    cudaEventDisableTiming);
    }

    cudaEventRecord(evFork, 0);
    cudaStreamWaitEvent(s1, evFork, 0);
    cudaStreamWaitEvent(s2, evFork, 0);

    // ---- s1: misc + merged CSR build ----
    misc_kernel<<<1, 1024, 0, s1>>>(Mmat, outA, ker_W, pth);
    zero_both_kernel<<<256, 256, 0, s1>>>(pcnt1, n1, pcnt2, n2);
    count_both_kernel<<<(E1 + E2 + 255)/256, 256, 0, s1>>>(e1dst, E1, e2dst, E2, pcnt1, pcnt2);
    {
        int B1 = (n1 + 4095)/4096;
        int B2 = (n2 + 4095)/4096;
        scan1_both_kernel<<<B1 + B2, 1024, 0, s1>>>(pcnt1, prp1, n1, B1, pcnt2, prp2, n2, ppart);
        scan2_both_kernel<<<1, 64, 0, s1>>>(ppart, B1, B2);
        scan3_both_kernel<<<(n1 + n2 + 255)/256, 256, 0, s1>>>(
            prp1, pcnt1, pcur1, pd1, n1, prp2, pcnt2, pcur2, pd2, n2, ppart);
    }
    scatter_both_kernel<<<(E1 + E2 + 255)/256, 256, 0, s1>>>(
        e1src, e1dst, E1, pcur1, pei1, e2src, e2dst, E2, pcur2, pei2);
    cudaEventRecord(evJoin1, s1);

    // ---- s2: pre MLP for x2 ----
    const int smemPre = (35*128 + 128*128 + 128*34 + 128 + 128 + 48) * 4;
    cudaFuncSetAttribute(pre_kernel, cudaFuncAttributeMaxDynamicSharedMemorySize, smemPre);
    pre_kernel<<<64, 256, smemPre, s2>>>(x2_cat, x2_num, n2,
        pre_W1, pre_b1, pre_W2, pre_b2, pre_W3, pre_b3, emb0, emb1, emb2, px2p);
    cudaEventRecord(evPre2, s2);

    // ---- main: pre MLP x1 ----
    pre_kernel<<<296, 256, smemPre>>>(x1_cat, x1_num, n1,
        pre_W1, pre_b1, pre_W2, pre_b2, pre_W3, pre_b3, emb0, emb1, emb2, px);

    cudaStreamWaitEvent(0, evJoin1, 0);

    // GCN1: fused gather+W1+relu+W2 -> hw2 (stride 36), then aggregate + bias
    gather_mm35_w2_kernel<<<(n1 + 15)/16, 512>>>(px, prp1, pcnt1, pei1, pd1,
                                                 g1_W1, g1_b1, g1_W2, 34, pA, n1);
    gather_kernel<<<(n1 + 15)/16, 512>>>(pA, 36, 34, prp1, pcnt1, pei1, pd1,
                                         g1_b2, pC, 36, n1, 0);

    // alpha (produces x2n)
    cudaStreamWaitEvent(0, evPre2, 0);
    alpha_kernel<<<SBK, 256>>>(pC, px2p, px, pth, outA, smoothing, px2n);
    cudaEventRecord(evAlpha, 0);

    // ---- s2: cd overlaps GCN2 chain ----
    cudaStreamWaitEvent(s2, evAlpha, 0);
    cd_kernel<<<SBK, 256, 0, s2>>>(px, px2n, outCD);
    cudaEventRecord(evCd, s2);

    // GCN2 on main stream
    gather_mm35_w2_kernel<<<(n2 + 15)/16, 512>>>(px2n, prp2, pcnt2, pei2, pd2,
                                                 g2_W1, g2_b1, g2_W2, 1, pA, n2);
    gather1_kernel<<<(n2 + 255)/256, 256>>>(pA, prp2, pcnt2, pei2, pd2, g2_b2, outO, n2);

    cudaStreamWaitEvent(0, evCd, 0);
}